// round 3
// baseline (speedup 1.0000x reference)
#include <cuda_runtime.h>
#include <math.h>
#include <stdint.h>

#define BSZ 4
#define SEQ 2048
#define DIM 1024
#define NH  16
#define DH  64

// ---------------------------------------------------------------------------
// Scratch (device globals; no allocations allowed)
// ---------------------------------------------------------------------------
__device__ float g_q  [(size_t)BSZ*NH*SEQ*DH];   // [b,h,s,d] (pre-scaled by 1/8)
__device__ float g_k  [(size_t)BSZ*NH*SEQ*DH];   // [b,h,s,d]
__device__ float g_v  [(size_t)BSZ*NH*SEQ*DH];   // [b,h,s,d]
__device__ float g_ctx[(size_t)BSZ*SEQ*DIM];     // [b,s,dim]
__device__ float g_m  [(size_t)BSZ*NH*SEQ];      // softmax row max
__device__ float g_rl [(size_t)BSZ*NH*SEQ];      // softmax 1/Z
__device__ float2 g_part[(size_t)BSZ*SEQ*16];    // per-(b,q,ktile) (val,idx)

#define OUT_PLAIN 0
#define OUT_QHEAD 1

// ---------------------------------------------------------------------------
// Helpers
// ---------------------------------------------------------------------------
__device__ __forceinline__ uint32_t f2tf(float x) {
    uint32_t r; asm("cvt.rna.tf32.f32 %0, %1;" : "=r"(r) : "f"(x)); return r;
}

__device__ __forceinline__ void mma8(float c[4], const uint32_t a[4], const uint32_t b[2]) {
    asm volatile(
        "mma.sync.aligned.m16n8k8.row.col.f32.tf32.tf32.f32 "
        "{%0,%1,%2,%3}, {%4,%5,%6,%7}, {%8,%9}, {%0,%1,%2,%3};"
        : "+f"(c[0]), "+f"(c[1]), "+f"(c[2]), "+f"(c[3])
        : "r"(a[0]), "r"(a[1]), "r"(a[2]), "r"(a[3]), "r"(b[0]), "r"(b[1]));
}

__device__ __forceinline__ void cpasync16(void* dst_smem, const void* src) {
    uint32_t d = (uint32_t)__cvta_generic_to_shared(dst_smem);
    asm volatile("cp.async.ca.shared.global [%0], [%1], 16;" :: "r"(d), "l"(src));
}

template<int MODE>
__device__ __forceinline__ void store_c(float* __restrict__ Cg, int z, int m, int n,
                                        int N, size_t sCz, float v)
{
    size_t idx;
    if (MODE == OUT_PLAIN) {
        idx = (size_t)z * sCz + (size_t)m * N + n;
    } else { // OUT_QHEAD
        int b = m >> 11, s = m & (SEQ-1);
        int h = n >> 6,  d = n & (DH-1);
        idx = (((size_t)(b*NH + h) * SEQ) + s) * DH + d;
    }
    Cg[idx] = v;
}

// ---------------------------------------------------------------------------
// TF32 tensor-core GEMM for projections: C = (A@B^T + bias) * scale
// ---------------------------------------------------------------------------
template<int BM, int BN, int BK, int WM, int WN, int THREE, int MODE>
__global__ void __launch_bounds__(WM*WN*32)
mma_tn(const float* __restrict__ Ag, const float* __restrict__ Bg,
       const float* __restrict__ bias, float* __restrict__ Cg,
       int M, int N, int K, float scale,
       size_t sAz, size_t sBz, size_t sCz)
{
    constexpr int NT   = WM*WN*32;
    constexpr int LDSM = BK + 4;
    constexpr int WTM  = BM/WM, WTN = BN/WN;
    constexpr int MI   = WTM/16, NI = WTN/8;

    extern __shared__ float smemf[];
    float* AsBuf[2] = { smemf, smemf + (size_t)(BM+BN)*LDSM };
    float* BsBuf[2] = { smemf + (size_t)BM*LDSM,
                        smemf + (size_t)(BM+BN)*LDSM + (size_t)BM*LDSM };

    const int z = blockIdx.z;
    const float* A = Ag + (size_t)z * sAz;
    const float* B = Bg + (size_t)z * sBz;
    const int bm0 = blockIdx.y * BM;
    const int bn0 = blockIdx.x * BN;
    const int tid = threadIdx.x, lane = tid & 31, warp = tid >> 5;
    const int wm0 = (warp / WN) * WTM;
    const int wn0 = (warp % WN) * WTN;
    const int g = lane >> 2, t = lane & 3;

    float acc[MI][NI][4];
    #pragma unroll
    for (int i = 0; i < MI; i++)
        #pragma unroll
        for (int j = 0; j < NI; j++)
            #pragma unroll
            for (int r = 0; r < 4; r++) acc[i][j][r] = 0.f;

    auto load_stage = [&](int k0, int s) {
        #pragma unroll 4
        for (int i = tid; i < BM*BK/4; i += NT) {
            int row = i / (BK/4), c4 = (i % (BK/4)) * 4;
            cpasync16(&AsBuf[s][row*LDSM + c4], &A[(size_t)(bm0+row)*K + k0 + c4]);
        }
        #pragma unroll 4
        for (int i = tid; i < BN*BK/4; i += NT) {
            int row = i / (BK/4), c4 = (i % (BK/4)) * 4;
            cpasync16(&BsBuf[s][row*LDSM + c4], &B[(size_t)(bn0+row)*K + k0 + c4]);
        }
        asm volatile("cp.async.commit_group;");
    };

    const int nk = K / BK;
    load_stage(0, 0);

    for (int kt = 0; kt < nk; kt++) {
        const int s = kt & 1;
        if (kt + 1 < nk) {
            load_stage((kt+1)*BK, s ^ 1);
            asm volatile("cp.async.wait_group 1;");
        } else {
            asm volatile("cp.async.wait_group 0;");
        }
        __syncthreads();

        const float* As = AsBuf[s];
        const float* Bs = BsBuf[s];

        #pragma unroll
        for (int ks = 0; ks < BK/8; ks++) {
            const int kb = ks * 8;
            uint32_t ah[MI][4], al[MI][4];
            uint32_t bh[NI][2], bl[NI][2];

            #pragma unroll
            for (int i = 0; i < MI; i++) {
                const int r0 = wm0 + i*16 + g;
                float x0 = As[(size_t)r0     *LDSM + kb + t];
                float x1 = As[(size_t)(r0+8) *LDSM + kb + t];
                float x2 = As[(size_t)r0     *LDSM + kb + 4 + t];
                float x3 = As[(size_t)(r0+8) *LDSM + kb + 4 + t];
                ah[i][0] = f2tf(x0); ah[i][1] = f2tf(x1);
                ah[i][2] = f2tf(x2); ah[i][3] = f2tf(x3);
                if (THREE) {
                    al[i][0] = f2tf(x0 - __uint_as_float(ah[i][0]));
                    al[i][1] = f2tf(x1 - __uint_as_float(ah[i][1]));
                    al[i][2] = f2tf(x2 - __uint_as_float(ah[i][2]));
                    al[i][3] = f2tf(x3 - __uint_as_float(ah[i][3]));
                }
            }
            #pragma unroll
            for (int j = 0; j < NI; j++) {
                const int c0 = wn0 + j*8 + g;
                float y0 = Bs[(size_t)c0*LDSM + kb + t];
                float y1 = Bs[(size_t)c0*LDSM + kb + 4 + t];
                bh[j][0] = f2tf(y0); bh[j][1] = f2tf(y1);
                if (THREE) {
                    bl[j][0] = f2tf(y0 - __uint_as_float(bh[j][0]));
                    bl[j][1] = f2tf(y1 - __uint_as_float(bh[j][1]));
                }
            }

            #pragma unroll
            for (int i = 0; i < MI; i++)
                #pragma unroll
                for (int j = 0; j < NI; j++)
                    mma8(acc[i][j], ah[i], bh[j]);
            if (THREE) {
                #pragma unroll
                for (int i = 0; i < MI; i++)
                    #pragma unroll
                    for (int j = 0; j < NI; j++) {
                        mma8(acc[i][j], ah[i], bl[j]);
                        mma8(acc[i][j], al[i], bh[j]);
                    }
            }
        }
        __syncthreads();
    }

    #pragma unroll
    for (int i = 0; i < MI; i++) {
        #pragma unroll
        for (int j = 0; j < NI; j++) {
            const int m0 = bm0 + wm0 + i*16 + g;
            const int n0 = bn0 + wn0 + j*8 + 2*t;
            float v0 = acc[i][j][0], v1 = acc[i][j][1];
            float v2 = acc[i][j][2], v3 = acc[i][j][3];
            if (bias) {
                v0 += bias[n0]; v1 += bias[n0+1];
                v2 += bias[n0]; v3 += bias[n0+1];
            }
            v0 *= scale; v1 *= scale; v2 *= scale; v3 *= scale;
            store_c<MODE>(Cg, z, m0,   n0,   N, sCz, v0);
            store_c<MODE>(Cg, z, m0,   n0+1, N, sCz, v1);
            store_c<MODE>(Cg, z, m0+8, n0,   N, sCz, v2);
            store_c<MODE>(Cg, z, m0+8, n0+1, N, sCz, v3);
        }
    }
}

// ---------------------------------------------------------------------------
// Flash attention: per (b,h,q-tile 128). S via 3xTF32, online softmax,
// P@V via tf32. Writes ctx + per-row (m, 1/Z).
// ---------------------------------------------------------------------------
#define QP 68
#define KP 68
#define VP 72

__global__ void __launch_bounds__(256, 1)
flash_kernel(const float* __restrict__ Qg, const float* __restrict__ Kg,
             const float* __restrict__ Vg, const int* __restrict__ mask,
             float* __restrict__ ctx, float* __restrict__ gm, float* __restrict__ grl)
{
    extern __shared__ float sm[];
    float* Qs    = sm;                        // 128*68 = 8704
    float* KsB[2]= { sm + 8704,  sm + 17408 };
    float* VsB[2]= { sm + 26112, sm + 35328 };
    int*   MsB[2]= { (int*)(sm + 44544), (int*)(sm + 44544) + 128 };

    const int bh = blockIdx.y;
    const int b  = bh >> 4, h = bh & 15;
    const int q0 = blockIdx.x * 128;
    const size_t base = (size_t)bh * SEQ * DH;
    const int tid = threadIdx.x, lane = tid & 31, warp = tid >> 5;
    const int g = lane >> 2, t = lane & 3;
    const int wr = warp * 16;

    auto ldKV = [&](int kt, int s) {
        const float* sk = Kg + base + (size_t)(kt*128) * DH;
        const float* sv = Vg + base + (size_t)(kt*128) * DH;
        #pragma unroll 4
        for (int i = tid; i < 2048; i += 256) {
            int r = i >> 4, c4 = (i & 15) * 4;
            cpasync16(&KsB[s][r*KP + c4], sk + (size_t)r*DH + c4);
        }
        #pragma unroll 4
        for (int i = tid; i < 2048; i += 256) {
            int r = i >> 4, c4 = (i & 15) * 4;
            cpasync16(&VsB[s][r*VP + c4], sv + (size_t)r*DH + c4);
        }
        if (tid < 32)
            cpasync16(&MsB[s][tid*4], mask + (size_t)b*SEQ + kt*128 + tid*4);
        asm volatile("cp.async.commit_group;");
    };

    // Q tile (own commit group)
    {
        const float* sq = Qg + base + (size_t)q0 * DH;
        #pragma unroll 4
        for (int i = tid; i < 2048; i += 256) {
            int r = i >> 4, c4 = (i & 15) * 4;
            cpasync16(&Qs[r*QP + c4], sq + (size_t)r*DH + c4);
        }
        asm volatile("cp.async.commit_group;");
    }
    ldKV(0, 0);
    ldKV(1, 1);
    asm volatile("cp.async.wait_group 1;");   // Q + stage0 ready
    __syncthreads();

    // Q fragments (hi/lo), register-resident
    uint32_t qh[8][4], ql[8][4];
    #pragma unroll
    for (int kc = 0; kc < 8; kc++) {
        float x0 = Qs[(wr+g)  *QP + kc*8 + t];
        float x1 = Qs[(wr+8+g)*QP + kc*8 + t];
        float x2 = Qs[(wr+g)  *QP + kc*8 + 4 + t];
        float x3 = Qs[(wr+8+g)*QP + kc*8 + 4 + t];
        qh[kc][0] = f2tf(x0); qh[kc][1] = f2tf(x1);
        qh[kc][2] = f2tf(x2); qh[kc][3] = f2tf(x3);
        ql[kc][0] = f2tf(x0 - __uint_as_float(qh[kc][0]));
        ql[kc][1] = f2tf(x1 - __uint_as_float(qh[kc][1]));
        ql[kc][2] = f2tf(x2 - __uint_as_float(qh[kc][2]));
        ql[kc][3] = f2tf(x3 - __uint_as_float(qh[kc][3]));
    }

    float oacc[8][4];
    #pragma unroll
    for (int dj = 0; dj < 8; dj++)
        #pragma unroll
        for (int r = 0; r < 4; r++) oacc[dj][r] = 0.f;
    float m0 = -INFINITY, m1 = -INFINITY, l0 = 0.f, l1 = 0.f;

    for (int kt = 0; kt < 16; kt++) {
        const int s = kt & 1;
        if (kt > 0) {
            asm volatile("cp.async.wait_group 1;");
            __syncthreads();
        }
        const float* Ks = KsB[s];
        const float* Vs = VsB[s];
        const int*   Mi = MsB[s];

        // S = Q K^T (3xTF32)
        float sacc[16][4];
        #pragma unroll
        for (int j = 0; j < 16; j++)
            #pragma unroll
            for (int r = 0; r < 4; r++) sacc[j][r] = 0.f;

        #pragma unroll
        for (int kc = 0; kc < 8; kc++) {
            #pragma unroll
            for (int j = 0; j < 16; j++) {
                float y0 = Ks[(j*8+g)*KP + kc*8 + t];
                float y1 = Ks[(j*8+g)*KP + kc*8 + 4 + t];
                uint32_t bhv[2] = { f2tf(y0), f2tf(y1) };
                uint32_t blv[2] = { f2tf(y0 - __uint_as_float(bhv[0])),
                                    f2tf(y1 - __uint_as_float(bhv[1])) };
                mma8(sacc[j], qh[kc], bhv);
                mma8(sacc[j], qh[kc], blv);
                mma8(sacc[j], ql[kc], bhv);
            }
        }

        // mask + row max
        float mx0 = -INFINITY, mx1 = -INFINITY;
        #pragma unroll
        for (int j = 0; j < 16; j++) {
            float a0 = (Mi[j*8 + 2*t]     == 0) ? -1e30f : 0.f;
            float a1 = (Mi[j*8 + 2*t + 1] == 0) ? -1e30f : 0.f;
            sacc[j][0] += a0; sacc[j][1] += a1;
            sacc[j][2] += a0; sacc[j][3] += a1;
            mx0 = fmaxf(mx0, fmaxf(sacc[j][0], sacc[j][1]));
            mx1 = fmaxf(mx1, fmaxf(sacc[j][2], sacc[j][3]));
        }
        mx0 = fmaxf(mx0, __shfl_xor_sync(0xffffffffu, mx0, 1));
        mx0 = fmaxf(mx0, __shfl_xor_sync(0xffffffffu, mx0, 2));
        mx1 = fmaxf(mx1, __shfl_xor_sync(0xffffffffu, mx1, 1));
        mx1 = fmaxf(mx1, __shfl_xor_sync(0xffffffffu, mx1, 2));

        const float nm0 = fmaxf(m0, mx0), nm1 = fmaxf(m1, mx1);
        const float al0 = __expf(m0 - nm0), al1 = __expf(m1 - nm1);
        m0 = nm0; m1 = nm1;

        float rs0 = 0.f, rs1 = 0.f;
        #pragma unroll
        for (int j = 0; j < 16; j++) {
            sacc[j][0] = __expf(sacc[j][0] - nm0);
            sacc[j][1] = __expf(sacc[j][1] - nm0);
            sacc[j][2] = __expf(sacc[j][2] - nm1);
            sacc[j][3] = __expf(sacc[j][3] - nm1);
            rs0 += sacc[j][0] + sacc[j][1];
            rs1 += sacc[j][2] + sacc[j][3];
        }
        rs0 += __shfl_xor_sync(0xffffffffu, rs0, 1);
        rs0 += __shfl_xor_sync(0xffffffffu, rs0, 2);
        rs1 += __shfl_xor_sync(0xffffffffu, rs1, 1);
        rs1 += __shfl_xor_sync(0xffffffffu, rs1, 2);
        l0 = l0 * al0 + rs0;
        l1 = l1 * al1 + rs1;

        #pragma unroll
        for (int dj = 0; dj < 8; dj++) {
            oacc[dj][0] *= al0; oacc[dj][1] *= al0;
            oacc[dj][2] *= al1; oacc[dj][3] *= al1;
        }

        // P @ V : convert C-layout P frags to A-layout via quad shuffles
        const int src1 = (lane & ~3) | (t >> 1);
        const int src2 = src1 + 2;
        const bool odd = (t & 1);
        #pragma unroll
        for (int j = 0; j < 16; j++) {
            float v0 = __shfl_sync(0xffffffffu, sacc[j][0], src1);
            float v1 = __shfl_sync(0xffffffffu, sacc[j][1], src1);
            float v2 = __shfl_sync(0xffffffffu, sacc[j][2], src1);
            float v3 = __shfl_sync(0xffffffffu, sacc[j][3], src1);
            float w0 = __shfl_sync(0xffffffffu, sacc[j][0], src2);
            float w1 = __shfl_sync(0xffffffffu, sacc[j][1], src2);
            float w2 = __shfl_sync(0xffffffffu, sacc[j][2], src2);
            float w3 = __shfl_sync(0xffffffffu, sacc[j][3], src2);
            uint32_t pa[4] = { f2tf(odd ? v1 : v0), f2tf(odd ? v3 : v2),
                               f2tf(odd ? w1 : w0), f2tf(odd ? w3 : w2) };
            #pragma unroll
            for (int dj = 0; dj < 8; dj++) {
                float z0 = Vs[(j*8 + t)  *VP + dj*8 + g];
                float z1 = Vs[(j*8 + t+4)*VP + dj*8 + g];
                uint32_t vb[2] = { f2tf(z0), f2tf(z1) };
                mma8(oacc[dj], pa, vb);
            }
        }

        __syncthreads();
        if (kt + 2 < 16) ldKV(kt + 2, s);
    }

    // Epilogue
    const float i0 = 1.f / l0, i1 = 1.f / l1;
    const int row0 = q0 + wr + g, row1 = row0 + 8;
    #pragma unroll
    for (int dj = 0; dj < 8; dj++) {
        const int col = h*64 + dj*8 + 2*t;
        float2 s0 = { oacc[dj][0]*i0, oacc[dj][1]*i0 };
        float2 s1 = { oacc[dj][2]*i1, oacc[dj][3]*i1 };
        *reinterpret_cast<float2*>(&ctx[((size_t)b*SEQ + row0)*DIM + col]) = s0;
        *reinterpret_cast<float2*>(&ctx[((size_t)b*SEQ + row1)*DIM + col]) = s1;
    }
    if (t == 0) {
        gm [(size_t)bh*SEQ + row0] = m0;  grl[(size_t)bh*SEQ + row0] = i0;
        gm [(size_t)bh*SEQ + row1] = m1;  grl[(size_t)bh*SEQ + row1] = i1;
    }
}

// ---------------------------------------------------------------------------
// Pass 2: per (b, q-tile, k-tile), recompute 3xTF32 scores for all heads,
// accumulate sum_h exp(s-m)/Z, per-row partial argmax -> g_part.
// ---------------------------------------------------------------------------
__global__ void __launch_bounds__(256, 1)
wsum_argmax_kernel(const float* __restrict__ Qg, const float* __restrict__ Kg,
                   const int* __restrict__ mask,
                   const float* __restrict__ gm, const float* __restrict__ grl,
                   float2* __restrict__ part)
{
    extern __shared__ float sm[];
    float* QsB[2] = { sm,         sm + 8704  };
    float* KsB[2] = { sm + 17408, sm + 26112 };
    int*   Mi     = (int*)(sm + 34816);

    const int b  = blockIdx.z;
    const int q0 = blockIdx.y * 128;
    const int kt = blockIdx.x;
    const int k0 = kt * 128;
    const int tid = threadIdx.x, lane = tid & 31, warp = tid >> 5;
    const int g = lane >> 2, t = lane & 3;
    const int wr = warp * 16;

    if (tid < 128) Mi[tid] = mask[(size_t)b*SEQ + k0 + tid];

    auto ldQK = [&](int h, int s) {
        const size_t base = ((size_t)(b*NH + h)) * SEQ * DH;
        const float* sq = Qg + base + (size_t)q0 * DH;
        const float* sk = Kg + base + (size_t)k0 * DH;
        #pragma unroll 4
        for (int i = tid; i < 2048; i += 256) {
            int r = i >> 4, c4 = (i & 15) * 4;
            cpasync16(&QsB[s][r*QP + c4], sq + (size_t)r*DH + c4);
        }
        #pragma unroll 4
        for (int i = tid; i < 2048; i += 256) {
            int r = i >> 4, c4 = (i & 15) * 4;
            cpasync16(&KsB[s][r*KP + c4], sk + (size_t)r*DH + c4);
        }
        asm volatile("cp.async.commit_group;");
    };

    ldQK(0, 0);
    ldQK(1, 1);

    float wacc[16][4];
    #pragma unroll
    for (int j = 0; j < 16; j++)
        #pragma unroll
        for (int r = 0; r < 4; r++) wacc[j][r] = 0.f;

    for (int h = 0; h < NH; h++) {
        const int s = h & 1;
        asm volatile("cp.async.wait_group 1;");
        __syncthreads();
        const float* Qs = QsB[s];
        const float* Ks = KsB[s];

        uint32_t qh[8][4], ql[8][4];
        #pragma unroll
        for (int kc = 0; kc < 8; kc++) {
            float x0 = Qs[(wr+g)  *QP + kc*8 + t];
            float x1 = Qs[(wr+8+g)*QP + kc*8 + t];
            float x2 = Qs[(wr+g)  *QP + kc*8 + 4 + t];
            float x3 = Qs[(wr+8+g)*QP + kc*8 + 4 + t];
            qh[kc][0] = f2tf(x0); qh[kc][1] = f2tf(x1);
            qh[kc][2] = f2tf(x2); qh[kc][3] = f2tf(x3);
            ql[kc][0] = f2tf(x0 - __uint_as_float(qh[kc][0]));
            ql[kc][1] = f2tf(x1 - __uint_as_float(qh[kc][1]));
            ql[kc][2] = f2tf(x2 - __uint_as_float(qh[kc][2]));
            ql[kc][3] = f2tf(x3 - __uint_as_float(qh[kc][3]));
        }

        const size_t srow = ((size_t)(b*NH + h)) * SEQ + q0 + wr + g;
        const float mr0 = gm[srow],     rl0 = grl[srow];
        const float mr1 = gm[srow + 8], rl1 = grl[srow + 8];

        #pragma unroll
        for (int j = 0; j < 16; j++) {
            float sacc[4] = {0.f, 0.f, 0.f, 0.f};
            #pragma unroll
            for (int kc = 0; kc < 8; kc++) {
                float y0 = Ks[(j*8+g)*KP + kc*8 + t];
                float y1 = Ks[(j*8+g)*KP + kc*8 + 4 + t];
                uint32_t bhv[2] = { f2tf(y0), f2tf(y1) };
                uint32_t blv[2] = { f2tf(y0 - __uint_as_float(bhv[0])),
                                    f2tf(y1 - __uint_as_float(bhv[1])) };
                mma8(sacc, qh[kc], bhv);
                mma8(sacc, qh[kc], blv);
                mma8(sacc, ql[kc], bhv);
            }
            float a0 = (Mi[j*8 + 2*t]     == 0) ? -1e30f : 0.f;
            float a1 = (Mi[j*8 + 2*t + 1] == 0) ? -1e30f : 0.f;
            wacc[j][0] += __expf(sacc[0] + a0 - mr0) * rl0;
            wacc[j][1] += __expf(sacc[1] + a1 - mr0) * rl0;
            wacc[j][2] += __expf(sacc[2] + a0 - mr1) * rl1;
            wacc[j][3] += __expf(sacc[3] + a1 - mr1) * rl1;
        }
        __syncthreads();
        if (h + 2 < NH) ldQK(h + 2, s);
    }

    // per-row argmax over this k-tile (first index on ties)
    float bv0 = -1.f, bv1 = -1.f;
    int   bi0 = 0,    bi1 = 0;
    #pragma unroll
    for (int j = 0; j < 16; j++) {
        int c0 = k0 + j*8 + 2*t, c1 = c0 + 1;
        if (wacc[j][0] > bv0) { bv0 = wacc[j][0]; bi0 = c0; }
        if (wacc[j][1] > bv0) { bv0 = wacc[j][1]; bi0 = c1; }
        if (wacc[j][2] > bv1) { bv1 = wacc[j][2]; bi1 = c0; }
        if (wacc[j][3] > bv1) { bv1 = wacc[j][3]; bi1 = c1; }
    }
    #pragma unroll
    for (int off = 1; off <= 2; off <<= 1) {
        float ov = __shfl_xor_sync(0xffffffffu, bv0, off);
        int   oi = __shfl_xor_sync(0xffffffffu, bi0, off);
        if (ov > bv0 || (ov == bv0 && oi < bi0)) { bv0 = ov; bi0 = oi; }
        ov = __shfl_xor_sync(0xffffffffu, bv1, off);
        oi = __shfl_xor_sync(0xffffffffu, bi1, off);
        if (ov > bv1 || (ov == bv1 && oi < bi1)) { bv1 = ov; bi1 = oi; }
    }
    if (t == 0) {
        part[((size_t)b*SEQ + q0 + wr + g)     * 16 + kt] = make_float2(bv0, (float)bi0);
        part[((size_t)b*SEQ + q0 + wr + 8 + g) * 16 + kt] = make_float2(bv1, (float)bi1);
    }
}

__global__ void __launch_bounds__(256)
final_argmax_kernel(const float2* __restrict__ part, float* __restrict__ outIdx)
{
    const int i = blockIdx.x * blockDim.x + threadIdx.x;
    if (i >= BSZ*SEQ) return;
    const float2* p = part + (size_t)i * 16;
    float bv = -1.f, bi = 0.f;
    #pragma unroll
    for (int kt = 0; kt < 16; kt++) {
        float2 v = p[kt];
        if (v.x > bv) { bv = v.x; bi = v.y; }
    }
    outIdx[i] = bi;
}

// ---------------------------------------------------------------------------
// Launch
// ---------------------------------------------------------------------------
extern "C" void kernel_launch(void* const* d_in, const int* in_sizes, int n_in,
                              void* d_out, int out_size)
{
    const float* X    = (const float*)d_in[0];
    const int*   mask = (const int*)  d_in[1];
    const float* Wq   = (const float*)d_in[2];
    const float* bq   = (const float*)d_in[3];
    const float* Wk   = (const float*)d_in[4];
    const float* bk   = (const float*)d_in[5];
    const float* Wv   = (const float*)d_in[6];
    const float* bv   = (const float*)d_in[7];
    const float* Wo   = (const float*)d_in[8];
    const float* bo   = (const float*)d_in[9];
    float* out = (float*)d_out;

    static float *pq=nullptr,*pk=nullptr,*pv=nullptr,*pctx=nullptr,*pm=nullptr,*prl=nullptr;
    static float2* ppart = nullptr;
    if (!pq) {
        cudaGetSymbolAddress((void**)&pq,   g_q);
        cudaGetSymbolAddress((void**)&pk,   g_k);
        cudaGetSymbolAddress((void**)&pv,   g_v);
        cudaGetSymbolAddress((void**)&pctx, g_ctx);
        cudaGetSymbolAddress((void**)&pm,   g_m);
        cudaGetSymbolAddress((void**)&prl,  g_rl);
        cudaGetSymbolAddress((void**)&ppart,g_part);
    }

    const int M = BSZ * SEQ;           // 8192
    const float qscale = 1.0f / 8.0f;  // 1/sqrt(64)

    constexpr int SMEM_BIG   = (128 + 128) * 36 * 4 * 2;   // 73728
    constexpr int SMEM_FLASH = 179200;
    constexpr int SMEM_PASS2 = 34816*4 + 512;              // 139776

    static bool attr = false;
    if (!attr) {
        attr = true;
        cudaFuncSetAttribute(mma_tn<128,128,32,2,4,1,OUT_QHEAD>,
                             cudaFuncAttributeMaxDynamicSharedMemorySize, SMEM_BIG);
        cudaFuncSetAttribute(mma_tn<128,128,32,2,4,0,OUT_QHEAD>,
                             cudaFuncAttributeMaxDynamicSharedMemorySize, SMEM_BIG);
        cudaFuncSetAttribute(mma_tn<128,128,32,2,4,0,OUT_PLAIN>,
                             cudaFuncAttributeMaxDynamicSharedMemorySize, SMEM_BIG);
        cudaFuncSetAttribute(flash_kernel,
                             cudaFuncAttributeMaxDynamicSharedMemorySize, SMEM_FLASH);
        cudaFuncSetAttribute(wsum_argmax_kernel,
                             cudaFuncAttributeMaxDynamicSharedMemorySize, SMEM_PASS2);
    }

    // --- QKV projections ---
    {
        dim3 grid(DIM/128, M/128, 1);
        mma_tn<128,128,32,2,4,1,OUT_QHEAD><<<grid, 256, SMEM_BIG>>>(
            X, Wq, bq, pq, M, DIM, DIM, qscale, 0, 0, 0);
        mma_tn<128,128,32,2,4,1,OUT_QHEAD><<<grid, 256, SMEM_BIG>>>(
            X, Wk, bk, pk, M, DIM, DIM, 1.0f, 0, 0, 0);
        mma_tn<128,128,32,2,4,0,OUT_QHEAD><<<grid, 256, SMEM_BIG>>>(
            X, Wv, bv, pv, M, DIM, DIM, 1.0f, 0, 0, 0);
    }

    // --- Fused attention (ctx + softmax stats) ---
    {
        dim3 grid(SEQ/128, BSZ*NH);
        flash_kernel<<<grid, 256, SMEM_FLASH>>>(pq, pk, pv, mask, pctx, pm, prl);
    }

    // --- Head-sum argmax ---
    if (out_size >= BSZ*SEQ*DIM + BSZ*SEQ) {
        dim3 grid(16, SEQ/128, BSZ);
        wsum_argmax_kernel<<<grid, 256, SMEM_PASS2>>>(pq, pk, mask, pm, prl, ppart);
        final_argmax_kernel<<<(BSZ*SEQ + 255)/256, 256>>>(ppart, out + (size_t)BSZ*SEQ*DIM);
    }

    // --- Output projection ---
    {
        dim3 grid(DIM/128, M/128, 1);
        mma_tn<128,128,32,2,4,0,OUT_PLAIN><<<grid, 256, SMEM_BIG>>>(
            pctx, Wo, bo, out, M, DIM, DIM, 1.0f, 0, 0, 0);
    }
}

// round 4
// speedup vs baseline: 1.0741x; 1.0741x over previous
#include <cuda_runtime.h>
#include <math.h>
#include <stdint.h>

#define BSZ 4
#define SEQ 2048
#define DIM 1024
#define NH  16
#define DH  64

// ---------------------------------------------------------------------------
// Scratch (device globals; no allocations allowed)
// ---------------------------------------------------------------------------
__device__ uint32_t g_qh[(size_t)BSZ*NH*SEQ*DH];  // tf32 hi of q/8   [b,h,s,d]
__device__ uint32_t g_ql[(size_t)BSZ*NH*SEQ*DH];  // tf32 lo
__device__ uint32_t g_kh[(size_t)BSZ*NH*SEQ*DH];  // tf32 hi of k
__device__ uint32_t g_kl[(size_t)BSZ*NH*SEQ*DH];  // tf32 lo
__device__ uint32_t g_v32[(size_t)BSZ*NH*SEQ*DH]; // tf32-rounded v
__device__ float g_ctx[(size_t)BSZ*SEQ*DIM];      // [b,s,dim]
__device__ float g_m  [(size_t)BSZ*NH*SEQ];       // softmax row max
__device__ float g_rl [(size_t)BSZ*NH*SEQ];       // softmax 1/Z
__device__ float2 g_part[(size_t)BSZ*SEQ*32];     // per-(b,q,ktile64) (val,idx)

#define OUT_PLAIN  0
#define OUT_SPLIT  1   // tf32 hi/lo -> Ch/Cl, head-major layout
#define OUT_TF32   2   // tf32 rounded -> Ch, head-major layout

// ---------------------------------------------------------------------------
// Helpers
// ---------------------------------------------------------------------------
__device__ __forceinline__ uint32_t f2tf(float x) {
    uint32_t r; asm("cvt.rna.tf32.f32 %0, %1;" : "=r"(r) : "f"(x)); return r;
}

__device__ __forceinline__ void mma8(float c[4], const uint32_t a[4], const uint32_t b[2]) {
    asm volatile(
        "mma.sync.aligned.m16n8k8.row.col.f32.tf32.tf32.f32 "
        "{%0,%1,%2,%3}, {%4,%5,%6,%7}, {%8,%9}, {%0,%1,%2,%3};"
        : "+f"(c[0]), "+f"(c[1]), "+f"(c[2]), "+f"(c[3])
        : "r"(a[0]), "r"(a[1]), "r"(a[2]), "r"(a[3]), "r"(b[0]), "r"(b[1]));
}

__device__ __forceinline__ void cpasync16(void* dst_smem, const void* src) {
    uint32_t d = (uint32_t)__cvta_generic_to_shared(dst_smem);
    asm volatile("cp.async.ca.shared.global [%0], [%1], 16;" :: "r"(d), "l"(src));
}

__device__ __forceinline__ size_t qhead_idx(int m, int n) {
    int b = m >> 11, s = m & (SEQ-1);
    int h = n >> 6,  d = n & (DH-1);
    return (((size_t)(b*NH + h) * SEQ) + s) * DH + d;
}

// ---------------------------------------------------------------------------
// TF32 tensor-core GEMM for projections: C = (A@B^T + bias) * scale
// ---------------------------------------------------------------------------
template<int BM, int BN, int BK, int WM, int WN, int THREE, int MODE>
__global__ void __launch_bounds__(WM*WN*32)
mma_tn(const float* __restrict__ Ag, const float* __restrict__ Bg,
       const float* __restrict__ bias, float* __restrict__ Cg,
       uint32_t* __restrict__ Ch, uint32_t* __restrict__ Cl,
       int M, int N, int K, float scale)
{
    constexpr int NT   = WM*WN*32;
    constexpr int LDSM = BK + 4;
    constexpr int WTM  = BM/WM, WTN = BN/WN;
    constexpr int MI   = WTM/16, NI = WTN/8;

    extern __shared__ float smemf[];
    float* AsBuf[2] = { smemf, smemf + (size_t)(BM+BN)*LDSM };
    float* BsBuf[2] = { smemf + (size_t)BM*LDSM,
                        smemf + (size_t)(BM+BN)*LDSM + (size_t)BM*LDSM };

    const float* A = Ag;
    const float* B = Bg;
    const int bm0 = blockIdx.y * BM;
    const int bn0 = blockIdx.x * BN;
    const int tid = threadIdx.x, lane = tid & 31, warp = tid >> 5;
    const int wm0 = (warp / WN) * WTM;
    const int wn0 = (warp % WN) * WTN;
    const int g = lane >> 2, t = lane & 3;

    float acc[MI][NI][4];
    #pragma unroll
    for (int i = 0; i < MI; i++)
        #pragma unroll
        for (int j = 0; j < NI; j++)
            #pragma unroll
            for (int r = 0; r < 4; r++) acc[i][j][r] = 0.f;

    auto load_stage = [&](int k0, int s) {
        #pragma unroll 4
        for (int i = tid; i < BM*BK/4; i += NT) {
            int row = i / (BK/4), c4 = (i % (BK/4)) * 4;
            cpasync16(&AsBuf[s][row*LDSM + c4], &A[(size_t)(bm0+row)*K + k0 + c4]);
        }
        #pragma unroll 4
        for (int i = tid; i < BN*BK/4; i += NT) {
            int row = i / (BK/4), c4 = (i % (BK/4)) * 4;
            cpasync16(&BsBuf[s][row*LDSM + c4], &B[(size_t)(bn0+row)*K + k0 + c4]);
        }
        asm volatile("cp.async.commit_group;");
    };

    const int nk = K / BK;
    load_stage(0, 0);

    for (int kt = 0; kt < nk; kt++) {
        const int s = kt & 1;
        if (kt + 1 < nk) {
            load_stage((kt+1)*BK, s ^ 1);
            asm volatile("cp.async.wait_group 1;");
        } else {
            asm volatile("cp.async.wait_group 0;");
        }
        __syncthreads();

        const float* As = AsBuf[s];
        const float* Bs = BsBuf[s];

        #pragma unroll
        for (int ks = 0; ks < BK/8; ks++) {
            const int kb = ks * 8;
            uint32_t ah[MI][4], al[MI][4];
            uint32_t bh[NI][2], bl[NI][2];

            #pragma unroll
            for (int i = 0; i < MI; i++) {
                const int r0 = wm0 + i*16 + g;
                float x0 = As[(size_t)r0     *LDSM + kb + t];
                float x1 = As[(size_t)(r0+8) *LDSM + kb + t];
                float x2 = As[(size_t)r0     *LDSM + kb + 4 + t];
                float x3 = As[(size_t)(r0+8) *LDSM + kb + 4 + t];
                ah[i][0] = f2tf(x0); ah[i][1] = f2tf(x1);
                ah[i][2] = f2tf(x2); ah[i][3] = f2tf(x3);
                if (THREE) {
                    al[i][0] = f2tf(x0 - __uint_as_float(ah[i][0]));
                    al[i][1] = f2tf(x1 - __uint_as_float(ah[i][1]));
                    al[i][2] = f2tf(x2 - __uint_as_float(ah[i][2]));
                    al[i][3] = f2tf(x3 - __uint_as_float(ah[i][3]));
                }
            }
            #pragma unroll
            for (int j = 0; j < NI; j++) {
                const int c0 = wn0 + j*8 + g;
                float y0 = Bs[(size_t)c0*LDSM + kb + t];
                float y1 = Bs[(size_t)c0*LDSM + kb + 4 + t];
                bh[j][0] = f2tf(y0); bh[j][1] = f2tf(y1);
                if (THREE) {
                    bl[j][0] = f2tf(y0 - __uint_as_float(bh[j][0]));
                    bl[j][1] = f2tf(y1 - __uint_as_float(bh[j][1]));
                }
            }

            #pragma unroll
            for (int i = 0; i < MI; i++)
                #pragma unroll
                for (int j = 0; j < NI; j++)
                    mma8(acc[i][j], ah[i], bh[j]);
            if (THREE) {
                #pragma unroll
                for (int i = 0; i < MI; i++)
                    #pragma unroll
                    for (int j = 0; j < NI; j++) {
                        mma8(acc[i][j], ah[i], bl[j]);
                        mma8(acc[i][j], al[i], bh[j]);
                    }
            }
        }
        __syncthreads();
    }

    #pragma unroll
    for (int i = 0; i < MI; i++) {
        #pragma unroll
        for (int j = 0; j < NI; j++) {
            const int m0 = bm0 + wm0 + i*16 + g;
            const int n0 = bn0 + wn0 + j*8 + 2*t;
            #pragma unroll
            for (int r = 0; r < 4; r++) {
                const int m = m0 + (r >> 1) * 8;
                const int n = n0 + (r & 1);
                float v = acc[i][j][r];
                if (bias) v += bias[n];
                v *= scale;
                if (MODE == OUT_PLAIN) {
                    Cg[(size_t)m * N + n] = v;
                } else if (MODE == OUT_SPLIT) {
                    size_t idx = qhead_idx(m, n);
                    uint32_t hi = f2tf(v);
                    Ch[idx] = hi;
                    Cl[idx] = f2tf(v - __uint_as_float(hi));
                } else { // OUT_TF32
                    Ch[qhead_idx(m, n)] = f2tf(v);
                }
            }
        }
    }
}

// ---------------------------------------------------------------------------
// Flash attention, pre-split operands. Per (b,h,q-tile 128); 64-key tiles.
// No cvt in the loop: pure LDS + MMA + softmax math.
// ---------------------------------------------------------------------------
#define QP 68
#define KP 68
#define VP 72
#define FL_STAGE (2*64*KP + 64*VP + 64)   // KH+KL+V+mask per stage (u32)
#define FL_QH 0
#define FL_QL (128*QP)
#define FL_ST (2*128*QP)

__global__ void __launch_bounds__(256, 1)
flash_kernel(const uint32_t* __restrict__ Qh, const uint32_t* __restrict__ Ql,
             const uint32_t* __restrict__ Kh, const uint32_t* __restrict__ Kl,
             const uint32_t* __restrict__ Vv, const int* __restrict__ mask,
             float* __restrict__ ctx, float* __restrict__ gm, float* __restrict__ grl)
{
    extern __shared__ uint32_t su[];

    const int bh = blockIdx.y;
    const int b  = bh >> 4, h = bh & 15;
    const int q0 = blockIdx.x * 128;
    const size_t base = (size_t)bh * SEQ * DH;
    const int tid = threadIdx.x, lane = tid & 31, warp = tid >> 5;
    const int g = lane >> 2, t = lane & 3;
    const int wr = warp * 16;

    auto ldKV = [&](int kt, int s) {
        uint32_t* st = su + FL_ST + s * FL_STAGE;
        const uint32_t* sk  = Kh + base + (size_t)(kt*64) * DH;
        const uint32_t* skl = Kl + base + (size_t)(kt*64) * DH;
        const uint32_t* sv  = Vv + base + (size_t)(kt*64) * DH;
        #pragma unroll 4
        for (int i = tid; i < 1024; i += 256) {
            int r = i >> 4, c4 = (i & 15) * 4;
            cpasync16(&st[r*KP + c4], sk + (size_t)r*DH + c4);
        }
        #pragma unroll 4
        for (int i = tid; i < 1024; i += 256) {
            int r = i >> 4, c4 = (i & 15) * 4;
            cpasync16(&st[64*KP + r*KP + c4], skl + (size_t)r*DH + c4);
        }
        #pragma unroll 4
        for (int i = tid; i < 1024; i += 256) {
            int r = i >> 4, c4 = (i & 15) * 4;
            cpasync16(&st[2*64*KP + r*VP + c4], sv + (size_t)r*DH + c4);
        }
        if (tid < 16)
            cpasync16(&st[2*64*KP + 64*VP + tid*4],
                      mask + (size_t)b*SEQ + kt*64 + tid*4);
        asm volatile("cp.async.commit_group;");
    };

    // Q hi/lo tiles (own commit group)
    {
        const uint32_t* sq  = Qh + base + (size_t)q0 * DH;
        const uint32_t* sql = Ql + base + (size_t)q0 * DH;
        #pragma unroll 4
        for (int i = tid; i < 2048; i += 256) {
            int r = i >> 4, c4 = (i & 15) * 4;
            cpasync16(&su[FL_QH + r*QP + c4], sq + (size_t)r*DH + c4);
        }
        #pragma unroll 4
        for (int i = tid; i < 2048; i += 256) {
            int r = i >> 4, c4 = (i & 15) * 4;
            cpasync16(&su[FL_QL + r*QP + c4], sql + (size_t)r*DH + c4);
        }
        asm volatile("cp.async.commit_group;");
    }
    ldKV(0, 0);
    ldKV(1, 1);
    asm volatile("cp.async.wait_group 1;");   // Q + stage0 ready
    __syncthreads();

    // Q fragments, register-resident (pre-split)
    uint32_t qh[8][4], ql[8][4];
    #pragma unroll
    for (int kc = 0; kc < 8; kc++) {
        qh[kc][0] = su[FL_QH + (wr+g)  *QP + kc*8 + t];
        qh[kc][1] = su[FL_QH + (wr+8+g)*QP + kc*8 + t];
        qh[kc][2] = su[FL_QH + (wr+g)  *QP + kc*8 + 4 + t];
        qh[kc][3] = su[FL_QH + (wr+8+g)*QP + kc*8 + 4 + t];
        ql[kc][0] = su[FL_QL + (wr+g)  *QP + kc*8 + t];
        ql[kc][1] = su[FL_QL + (wr+8+g)*QP + kc*8 + t];
        ql[kc][2] = su[FL_QL + (wr+g)  *QP + kc*8 + 4 + t];
        ql[kc][3] = su[FL_QL + (wr+8+g)*QP + kc*8 + 4 + t];
    }

    float oacc[8][4];
    #pragma unroll
    for (int dj = 0; dj < 8; dj++)
        #pragma unroll
        for (int r = 0; r < 4; r++) oacc[dj][r] = 0.f;
    float m0 = -INFINITY, m1 = -INFINITY, l0 = 0.f, l1 = 0.f;

    for (int kt = 0; kt < 32; kt++) {
        const int s = kt & 1;
        if (kt > 0) {
            asm volatile("cp.async.wait_group 1;");
            __syncthreads();
        }
        const uint32_t* KsH = su + FL_ST + s * FL_STAGE;
        const uint32_t* KsL = KsH + 64*KP;
        const uint32_t* Vs  = KsH + 2*64*KP;
        const int*      Mi  = (const int*)(KsH + 2*64*KP + 64*VP);

        // S = Q K^T (3xTF32, zero cvt)
        float sacc[8][4];
        #pragma unroll
        for (int j = 0; j < 8; j++)
            #pragma unroll
            for (int r = 0; r < 4; r++) sacc[j][r] = 0.f;

        #pragma unroll
        for (int kc = 0; kc < 8; kc++) {
            #pragma unroll
            for (int j = 0; j < 8; j++) {
                uint32_t bh2[2] = { KsH[(j*8+g)*KP + kc*8 + t],
                                    KsH[(j*8+g)*KP + kc*8 + 4 + t] };
                uint32_t bl2[2] = { KsL[(j*8+g)*KP + kc*8 + t],
                                    KsL[(j*8+g)*KP + kc*8 + 4 + t] };
                mma8(sacc[j], qh[kc], bh2);
                mma8(sacc[j], qh[kc], bl2);
                mma8(sacc[j], ql[kc], bh2);
            }
        }

        // mask + row max
        float mx0 = -INFINITY, mx1 = -INFINITY;
        #pragma unroll
        for (int j = 0; j < 8; j++) {
            float a0 = (Mi[j*8 + 2*t]     == 0) ? -1e30f : 0.f;
            float a1 = (Mi[j*8 + 2*t + 1] == 0) ? -1e30f : 0.f;
            sacc[j][0] += a0; sacc[j][1] += a1;
            sacc[j][2] += a0; sacc[j][3] += a1;
            mx0 = fmaxf(mx0, fmaxf(sacc[j][0], sacc[j][1]));
            mx1 = fmaxf(mx1, fmaxf(sacc[j][2], sacc[j][3]));
        }
        mx0 = fmaxf(mx0, __shfl_xor_sync(0xffffffffu, mx0, 1));
        mx0 = fmaxf(mx0, __shfl_xor_sync(0xffffffffu, mx0, 2));
        mx1 = fmaxf(mx1, __shfl_xor_sync(0xffffffffu, mx1, 1));
        mx1 = fmaxf(mx1, __shfl_xor_sync(0xffffffffu, mx1, 2));

        const float nm0 = fmaxf(m0, mx0), nm1 = fmaxf(m1, mx1);
        const float al0 = __expf(m0 - nm0), al1 = __expf(m1 - nm1);
        m0 = nm0; m1 = nm1;

        float rs0 = 0.f, rs1 = 0.f;
        #pragma unroll
        for (int j = 0; j < 8; j++) {
            sacc[j][0] = __expf(sacc[j][0] - nm0);
            sacc[j][1] = __expf(sacc[j][1] - nm0);
            sacc[j][2] = __expf(sacc[j][2] - nm1);
            sacc[j][3] = __expf(sacc[j][3] - nm1);
            rs0 += sacc[j][0] + sacc[j][1];
            rs1 += sacc[j][2] + sacc[j][3];
        }
        rs0 += __shfl_xor_sync(0xffffffffu, rs0, 1);
        rs0 += __shfl_xor_sync(0xffffffffu, rs0, 2);
        rs1 += __shfl_xor_sync(0xffffffffu, rs1, 1);
        rs1 += __shfl_xor_sync(0xffffffffu, rs1, 2);
        l0 = l0 * al0 + rs0;
        l1 = l1 * al1 + rs1;

        #pragma unroll
        for (int dj = 0; dj < 8; dj++) {
            oacc[dj][0] *= al0; oacc[dj][1] *= al0;
            oacc[dj][2] *= al1; oacc[dj][3] *= al1;
        }

        // P @ V : C-layout -> A-layout via quad shuffles
        const int src1 = (lane & ~3) | (t >> 1);
        const int src2 = src1 + 2;
        const bool odd = (t & 1);
        #pragma unroll
        for (int j = 0; j < 8; j++) {
            float v0 = __shfl_sync(0xffffffffu, sacc[j][0], src1);
            float v1 = __shfl_sync(0xffffffffu, sacc[j][1], src1);
            float v2 = __shfl_sync(0xffffffffu, sacc[j][2], src1);
            float v3 = __shfl_sync(0xffffffffu, sacc[j][3], src1);
            float w0 = __shfl_sync(0xffffffffu, sacc[j][0], src2);
            float w1 = __shfl_sync(0xffffffffu, sacc[j][1], src2);
            float w2 = __shfl_sync(0xffffffffu, sacc[j][2], src2);
            float w3 = __shfl_sync(0xffffffffu, sacc[j][3], src2);
            uint32_t pa[4] = { f2tf(odd ? v1 : v0), f2tf(odd ? v3 : v2),
                               f2tf(odd ? w1 : w0), f2tf(odd ? w3 : w2) };
            #pragma unroll
            for (int dj = 0; dj < 8; dj++) {
                uint32_t vb[2] = { Vs[(j*8 + t)  *VP + dj*8 + g],
                                   Vs[(j*8 + t+4)*VP + dj*8 + g] };
                mma8(oacc[dj], pa, vb);
            }
        }

        __syncthreads();
        if (kt + 2 < 32) ldKV(kt + 2, s);
    }

    // Epilogue
    const float i0 = 1.f / l0, i1 = 1.f / l1;
    const int row0 = q0 + wr + g, row1 = row0 + 8;
    #pragma unroll
    for (int dj = 0; dj < 8; dj++) {
        const int col = h*64 + dj*8 + 2*t;
        float2 s0 = { oacc[dj][0]*i0, oacc[dj][1]*i0 };
        float2 s1 = { oacc[dj][2]*i1, oacc[dj][3]*i1 };
        *reinterpret_cast<float2*>(&ctx[((size_t)b*SEQ + row0)*DIM + col]) = s0;
        *reinterpret_cast<float2*>(&ctx[((size_t)b*SEQ + row1)*DIM + col]) = s1;
    }
    if (t == 0) {
        gm [(size_t)bh*SEQ + row0] = m0;  grl[(size_t)bh*SEQ + row0] = i0;
        gm [(size_t)bh*SEQ + row1] = m1;  grl[(size_t)bh*SEQ + row1] = i1;
    }
}

// ---------------------------------------------------------------------------
// Pass 2: per (b, q-tile 128, k-tile 64); recompute scores per head from
// pre-split operands; accumulate sum_h exp(s-m)/Z; partial argmax -> g_part.
// ---------------------------------------------------------------------------
#define P2_STAGE (2*128*QP + 2*64*KP)

__global__ void __launch_bounds__(256, 1)
wsum_argmax_kernel(const uint32_t* __restrict__ Qh, const uint32_t* __restrict__ Ql,
                   const uint32_t* __restrict__ Kh, const uint32_t* __restrict__ Kl,
                   const int* __restrict__ mask,
                   const float* __restrict__ gm, const float* __restrict__ grl,
                   float2* __restrict__ part)
{
    extern __shared__ uint32_t su[];
    int* Mi = (int*)(su + 2*P2_STAGE);

    const int b  = blockIdx.z;
    const int q0 = blockIdx.y * 128;
    const int kt = blockIdx.x;
    const int k0 = kt * 64;
    const int tid = threadIdx.x, lane = tid & 31, warp = tid >> 5;
    const int g = lane >> 2, t = lane & 3;
    const int wr = warp * 16;

    if (tid < 64) Mi[tid] = mask[(size_t)b*SEQ + k0 + tid];

    auto ldQK = [&](int h, int s) {
        uint32_t* st = su + s * P2_STAGE;
        const size_t base = ((size_t)(b*NH + h)) * SEQ * DH;
        const uint32_t* sq  = Qh + base + (size_t)q0 * DH;
        const uint32_t* sql = Ql + base + (size_t)q0 * DH;
        const uint32_t* sk  = Kh + base + (size_t)k0 * DH;
        const uint32_t* skl = Kl + base + (size_t)k0 * DH;
        #pragma unroll 4
        for (int i = tid; i < 2048; i += 256) {
            int r = i >> 4, c4 = (i & 15) * 4;
            cpasync16(&st[r*QP + c4], sq + (size_t)r*DH + c4);
        }
        #pragma unroll 4
        for (int i = tid; i < 2048; i += 256) {
            int r = i >> 4, c4 = (i & 15) * 4;
            cpasync16(&st[128*QP + r*QP + c4], sql + (size_t)r*DH + c4);
        }
        #pragma unroll 4
        for (int i = tid; i < 1024; i += 256) {
            int r = i >> 4, c4 = (i & 15) * 4;
            cpasync16(&st[2*128*QP + r*KP + c4], sk + (size_t)r*DH + c4);
        }
        #pragma unroll 4
        for (int i = tid; i < 1024; i += 256) {
            int r = i >> 4, c4 = (i & 15) * 4;
            cpasync16(&st[2*128*QP + 64*KP + r*KP + c4], skl + (size_t)r*DH + c4);
        }
        asm volatile("cp.async.commit_group;");
    };

    ldQK(0, 0);
    ldQK(1, 1);

    float wacc[8][4];
    #pragma unroll
    for (int j = 0; j < 8; j++)
        #pragma unroll
        for (int r = 0; r < 4; r++) wacc[j][r] = 0.f;

    for (int h = 0; h < NH; h++) {
        const int s = h & 1;
        asm volatile("cp.async.wait_group 1;");
        __syncthreads();
        const uint32_t* QsH = su + s * P2_STAGE;
        const uint32_t* QsL = QsH + 128*QP;
        const uint32_t* KsH = QsH + 2*128*QP;
        const uint32_t* KsL = KsH + 64*KP;

        uint32_t qh[8][4], ql[8][4];
        #pragma unroll
        for (int kc = 0; kc < 8; kc++) {
            qh[kc][0] = QsH[(wr+g)  *QP + kc*8 + t];
            qh[kc][1] = QsH[(wr+8+g)*QP + kc*8 + t];
            qh[kc][2] = QsH[(wr+g)  *QP + kc*8 + 4 + t];
            qh[kc][3] = QsH[(wr+8+g)*QP + kc*8 + 4 + t];
            ql[kc][0] = QsL[(wr+g)  *QP + kc*8 + t];
            ql[kc][1] = QsL[(wr+8+g)*QP + kc*8 + t];
            ql[kc][2] = QsL[(wr+g)  *QP + kc*8 + 4 + t];
            ql[kc][3] = QsL[(wr+8+g)*QP + kc*8 + 4 + t];
        }

        const size_t srow = ((size_t)(b*NH + h)) * SEQ + q0 + wr + g;
        const float mr0 = gm[srow],     rl0 = grl[srow];
        const float mr1 = gm[srow + 8], rl1 = grl[srow + 8];

        #pragma unroll
        for (int j = 0; j < 8; j++) {
            float sacc[4] = {0.f, 0.f, 0.f, 0.f};
            #pragma unroll
            for (int kc = 0; kc < 8; kc++) {
                uint32_t bh2[2] = { KsH[(j*8+g)*KP + kc*8 + t],
                                    KsH[(j*8+g)*KP + kc*8 + 4 + t] };
                uint32_t bl2[2] = { KsL[(j*8+g)*KP + kc*8 + t],
                                    KsL[(j*8+g)*KP + kc*8 + 4 + t] };
                mma8(sacc, qh[kc], bh2);
                mma8(sacc, qh[kc], bl2);
                mma8(sacc, ql[kc], bh2);
            }
            float a0 = (Mi[j*8 + 2*t]     == 0) ? -1e30f : 0.f;
            float a1 = (Mi[j*8 + 2*t + 1] == 0) ? -1e30f : 0.f;
            wacc[j][0] += __expf(sacc[0] + a0 - mr0) * rl0;
            wacc[j][1] += __expf(sacc[1] + a1 - mr0) * rl0;
            wacc[j][2] += __expf(sacc[2] + a0 - mr1) * rl1;
            wacc[j][3] += __expf(sacc[3] + a1 - mr1) * rl1;
        }
        __syncthreads();
        if (h + 2 < NH) ldQK(h + 2, s);
    }

    // per-row argmax over this k-tile (first index on ties)
    float bv0 = -1.f, bv1 = -1.f;
    int   bi0 = 0,    bi1 = 0;
    #pragma unroll
    for (int j = 0; j < 8; j++) {
        int c0 = k0 + j*8 + 2*t, c1 = c0 + 1;
        if (wacc[j][0] > bv0) { bv0 = wacc[j][0]; bi0 = c0; }
        if (wacc[j][1] > bv0) { bv0 = wacc[j][1]; bi0 = c1; }
        if (wacc[j][2] > bv1) { bv1 = wacc[j][2]; bi1 = c0; }
        if (wacc[j][3] > bv1) { bv1 = wacc[j][3]; bi1 = c1; }
    }
    #pragma unroll
    for (int off = 1; off <= 2; off <<= 1) {
        float ov = __shfl_xor_sync(0xffffffffu, bv0, off);
        int   oi = __shfl_xor_sync(0xffffffffu, bi0, off);
        if (ov > bv0 || (ov == bv0 && oi < bi0)) { bv0 = ov; bi0 = oi; }
        ov = __shfl_xor_sync(0xffffffffu, bv1, off);
        oi = __shfl_xor_sync(0xffffffffu, bi1, off);
        if (ov > bv1 || (ov == bv1 && oi < bi1)) { bv1 = ov; bi1 = oi; }
    }
    if (t == 0) {
        part[((size_t)b*SEQ + q0 + wr + g)     * 32 + kt] = make_float2(bv0, (float)bi0);
        part[((size_t)b*SEQ + q0 + wr + 8 + g) * 32 + kt] = make_float2(bv1, (float)bi1);
    }
}

__global__ void __launch_bounds__(256)
final_argmax_kernel(const float2* __restrict__ part, float* __restrict__ outIdx)
{
    const int i = blockIdx.x * blockDim.x + threadIdx.x;
    if (i >= BSZ*SEQ) return;
    const float2* p = part + (size_t)i * 32;
    float bv = -1.f, bi = 0.f;
    #pragma unroll
    for (int kt = 0; kt < 32; kt++) {
        float2 v = p[kt];
        if (v.x > bv) { bv = v.x; bi = v.y; }
    }
    outIdx[i] = bi;
}

// ---------------------------------------------------------------------------
// Launch
// ---------------------------------------------------------------------------
extern "C" void kernel_launch(void* const* d_in, const int* in_sizes, int n_in,
                              void* d_out, int out_size)
{
    const float* X    = (const float*)d_in[0];
    const int*   mask = (const int*)  d_in[1];
    const float* Wq   = (const float*)d_in[2];
    const float* bq   = (const float*)d_in[3];
    const float* Wk   = (const float*)d_in[4];
    const float* bk   = (const float*)d_in[5];
    const float* Wv   = (const float*)d_in[6];
    const float* bv   = (const float*)d_in[7];
    const float* Wo   = (const float*)d_in[8];
    const float* bo   = (const float*)d_in[9];
    float* out = (float*)d_out;

    static uint32_t *pqh=nullptr,*pql=nullptr,*pkh=nullptr,*pkl=nullptr,*pv32=nullptr;
    static float *pctx=nullptr,*pm=nullptr,*prl=nullptr;
    static float2* ppart = nullptr;
    if (!pqh) {
        cudaGetSymbolAddress((void**)&pqh,  g_qh);
        cudaGetSymbolAddress((void**)&pql,  g_ql);
        cudaGetSymbolAddress((void**)&pkh,  g_kh);
        cudaGetSymbolAddress((void**)&pkl,  g_kl);
        cudaGetSymbolAddress((void**)&pv32, g_v32);
        cudaGetSymbolAddress((void**)&pctx, g_ctx);
        cudaGetSymbolAddress((void**)&pm,   g_m);
        cudaGetSymbolAddress((void**)&prl,  g_rl);
        cudaGetSymbolAddress((void**)&ppart,g_part);
    }

    const int M = BSZ * SEQ;           // 8192
    const float qscale = 1.0f / 8.0f;  // 1/sqrt(64)

    constexpr int SMEM_BIG   = (128 + 128) * 36 * 4 * 2;       // 73728
    constexpr int SMEM_FLASH = (FL_ST + 2*FL_STAGE) * 4;       // 176640
    constexpr int SMEM_PASS2 = (2*P2_STAGE + 64) * 4;          // 209152

    static bool attr = false;
    if (!attr) {
        attr = true;
        cudaFuncSetAttribute(mma_tn<128,128,32,2,4,1,OUT_SPLIT>,
                             cudaFuncAttributeMaxDynamicSharedMemorySize, SMEM_BIG);
        cudaFuncSetAttribute(mma_tn<128,128,32,2,4,0,OUT_TF32>,
                             cudaFuncAttributeMaxDynamicSharedMemorySize, SMEM_BIG);
        cudaFuncSetAttribute(mma_tn<128,128,32,2,4,0,OUT_PLAIN>,
                             cudaFuncAttributeMaxDynamicSharedMemorySize, SMEM_BIG);
        cudaFuncSetAttribute(flash_kernel,
                             cudaFuncAttributeMaxDynamicSharedMemorySize, SMEM_FLASH);
        cudaFuncSetAttribute(wsum_argmax_kernel,
                             cudaFuncAttributeMaxDynamicSharedMemorySize, SMEM_PASS2);
    }

    // --- QKV projections (write pre-split / pre-rounded tf32) ---
    {
        dim3 grid(DIM/128, M/128, 1);
        mma_tn<128,128,32,2,4,1,OUT_SPLIT><<<grid, 256, SMEM_BIG>>>(
            X, Wq, bq, nullptr, pqh, pql, M, DIM, DIM, qscale);
        mma_tn<128,128,32,2,4,1,OUT_SPLIT><<<grid, 256, SMEM_BIG>>>(
            X, Wk, bk, nullptr, pkh, pkl, M, DIM, DIM, 1.0f);
        mma_tn<128,128,32,2,4,0,OUT_TF32><<<grid, 256, SMEM_BIG>>>(
            X, Wv, bv, nullptr, pv32, nullptr, M, DIM, DIM, 1.0f);
    }

    // --- Fused attention (ctx + softmax stats) ---
    {
        dim3 grid(SEQ/128, BSZ*NH);
        flash_kernel<<<grid, 256, SMEM_FLASH>>>(pqh, pql, pkh, pkl, pv32, mask,
                                                pctx, pm, prl);
    }

    // --- Head-sum argmax ---
    if (out_size >= BSZ*SEQ*DIM + BSZ*SEQ) {
        dim3 grid(32, SEQ/128, BSZ);
        wsum_argmax_kernel<<<grid, 256, SMEM_PASS2>>>(pqh, pql, pkh, pkl, mask,
                                                      pm, prl, ppart);
        final_argmax_kernel<<<(BSZ*SEQ + 255)/256, 256>>>(ppart, out + (size_t)BSZ*SEQ*DIM);
    }

    // --- Output projection ---
    {
        dim3 grid(DIM/128, M/128, 1);
        mma_tn<128,128,32,2,4,0,OUT_PLAIN><<<grid, 256, SMEM_BIG>>>(
            pctx, Wo, bo, out, nullptr, nullptr, M, DIM, DIM, 1.0f);
    }
}